// round 12
// baseline (speedup 1.0000x reference)
#include <cuda_runtime.h>
#include <cstdint>
#include <cstddef>

typedef unsigned long long ull;
#define DI __device__ __forceinline__

DI ull pack2(float x, float y){ ull r; asm("mov.b64 %0,{%1,%2};":"=l"(r):"f"(x),"f"(y)); return r; }
DI float2 unp2(ull v){ float2 r; asm("mov.b64 {%0,%1},%2;":"=f"(r.x),"=f"(r.y):"l"(v)); return r; }
DI ull fma2(ull a, ull b, ull c){ ull d; asm("fma.rn.f32x2 %0,%1,%2,%3;":"=l"(d):"l"(a),"l"(b),"l"(c)); return d; }
DI ull mul2(ull a, ull b){ ull d; asm("mul.rn.f32x2 %0,%1,%2;":"=l"(d):"l"(a),"l"(b)); return d; }

DI void cpa16(void* dst_smem, const void* src_gmem){
    uint32_t s = (uint32_t)__cvta_generic_to_shared(dst_smem);
    asm volatile("cp.async.cg.shared.global [%0], [%1], 16;\n" :: "r"(s), "l"(src_gmem) : "memory");
}
DI void cpa_commit(){ asm volatile("cp.async.commit_group;\n" ::: "memory"); }
template<int N> DI void cpa_wait(){ asm volatile("cp.async.wait_group %0;\n" :: "n"(N) : "memory"); }

constexpr int B_ = 2, S_ = 512, H_ = 8, D_ = 32, DM_ = 256;
constexpr int M_ = B_ * S_;   // 1024 token rows

// Scratch (cudaMalloc forbidden)
__device__ float g_q [M_ * DM_];
__device__ float g_k [M_ * DM_];
__device__ float g_v [M_ * DM_];
__device__ float g_ao[M_ * DM_];
__device__ float g_s [(size_t)B_ * S_ * H_ * S_];   // scores [b][i][h][j] 16.8MB

// ---------------------------------------------------------------------------
// Kernel 1: QKV projections. out[m][n] = sum_k x[m][k] * w[k][n]
// 64x32 tiles (m x n), K-step 32, cp.async double-buffered, 4x4 reg tile.
// grid (8 n, 16 m, 3 mats), 128 threads.
// ---------------------------------------------------------------------------
__global__ void __launch_bounds__(128) qkv_k(const float* __restrict__ x,
                                             const float* __restrict__ wq,
                                             const float* __restrict__ wk,
                                             const float* __restrict__ wv)
{
    __shared__ float As[2][64][36];   // [buf][m][k] padded
    __shared__ float Bs[2][32][36];   // [buf][k][n] padded
    const int bz = blockIdx.z;
    const float* w = (bz == 0) ? wq : ((bz == 1) ? wk : wv);
    float* out = (bz == 0) ? g_q : ((bz == 1) ? g_k : g_v);
    const int m0 = blockIdx.y * 64, n0 = blockIdx.x * 32;
    const int tid = threadIdx.x, tx = tid & 7, ty = tid >> 3;   // tx: 8x4 cols, ty: 16x4 rows

    auto stage = [&](int kt){
        int buf = kt & 1, k0 = kt * 32;
        #pragma unroll
        for (int r = 0; r < 4; r++) {            // A: 64x32 = 512 chunks
            int f = r * 128 + tid; int row = f >> 3, kq = f & 7;
            cpa16(&As[buf][row][kq * 4], x + (size_t)(m0 + row) * DM_ + k0 + kq * 4);
        }
        #pragma unroll
        for (int r = 0; r < 2; r++) {            // B: 32x32 = 256 chunks
            int f = r * 128 + tid; int kk = f >> 3, nq = f & 7;
            cpa16(&Bs[buf][kk][nq * 4], w + (size_t)(k0 + kk) * DM_ + n0 + nq * 4);
        }
    };

    ull acc[4][2];
    #pragma unroll
    for (int r = 0; r < 4; r++) { acc[r][0] = 0ull; acc[r][1] = 0ull; }

    stage(0); cpa_commit();
    stage(1); cpa_commit();

    for (int kt = 0; kt < 8; kt++) {
        if (kt < 7) cpa_wait<1>(); else cpa_wait<0>();
        __syncthreads();
        const int buf = kt & 1;

        float4     aR[2][4];
        ulonglong2 bR[2][4];
        #pragma unroll
        for (int r = 0; r < 4; r++)
            aR[0][r] = *(const float4*)&As[buf][ty * 4 + r][0];
        #pragma unroll
        for (int kk = 0; kk < 4; kk++)
            bR[0][kk] = *(const ulonglong2*)&Bs[buf][kk][tx * 4];

        #pragma unroll
        for (int k4 = 0; k4 < 8; k4++) {
            const int cur = k4 & 1, nxt = cur ^ 1;
            if (k4 < 7) {
                #pragma unroll
                for (int r = 0; r < 4; r++)
                    aR[nxt][r] = *(const float4*)&As[buf][ty * 4 + r][(k4 + 1) * 4];
                #pragma unroll
                for (int kk = 0; kk < 4; kk++)
                    bR[nxt][kk] = *(const ulonglong2*)&Bs[buf][(k4 + 1) * 4 + kk][tx * 4];
            }
            #pragma unroll
            for (int kk = 0; kk < 4; kk++) {
                #pragma unroll
                for (int r = 0; r < 4; r++) {
                    float a = ((const float*)&aR[cur][r])[kk];
                    ull ap = pack2(a, a);
                    acc[r][0] = fma2(ap, bR[cur][kk].x, acc[r][0]);
                    acc[r][1] = fma2(ap, bR[cur][kk].y, acc[r][1]);
                }
            }
        }
        __syncthreads();
        if (kt + 2 < 8) { stage(kt + 2); cpa_commit(); }
    }
    #pragma unroll
    for (int r = 0; r < 4; r++) {
        float2 lo = unp2(acc[r][0]), hi = unp2(acc[r][1]);
        float4 o; o.x = lo.x; o.y = lo.y; o.z = hi.x; o.w = hi.y;
        *(float4*)(out + (size_t)(m0 + ty * 4 + r) * DM_ + n0 + tx * 4) = o;
    }
}

// ---------------------------------------------------------------------------
// Kernel 2a: score tiles. Block = (j-tile 32, i-tile 8, b). 256 threads.
// s[b,h,i,j] = sum_d q[b,h,j,d] * k[b,h,i,d] * rpe[b,i,j,d] / sqrt(D)
// Fully parallel: up to 1024 independent blocks, one tile each, single wait.
// Writes g_s[b][i][h][j]. Blocks with j0 >= station_num exit immediately.
// ---------------------------------------------------------------------------
constexpr int SJT = 32;
constexpr int SC_OFF_Q = 0;                      // q [32][292] (h-pad 36)
constexpr int SC_OFF_R = 32 * 292;               // rpe [8][32][36]
constexpr int SC_FLOATS = SC_OFF_R + 8 * 32 * 36;   // 18560
constexpr int SC_BYTES  = SC_FLOATS * 4;            // 74,240 B

__global__ void __launch_bounds__(256) score_k(const float* __restrict__ rpe,
                                               const int* __restrict__ snp)
{
    extern __shared__ float sm[];
    int sn = *snp; if (sn > 256) sn = 256; if (sn < 0) sn = 0;
    const int j0 = blockIdx.x * SJT;
    if (j0 >= sn) return;
    const int i0 = blockIdx.y * 8, b = blockIdx.z;
    const int tid = threadIdx.x, w = tid >> 5, lane = tid & 31;
    const int il = lane >> 3, h = lane & 7;
    const float scale = 0.17677669529663687f;

    // stage q rows j0..j0+31 (head-padded) and rpe [8i][32j][32d]
    #pragma unroll
    for (int r = 0; r < 8; r++) {
        int f = r * 256 + tid; int row = f >> 6, cq = f & 63;
        cpa16(sm + SC_OFF_Q + row * 292 + (cq >> 3) * 36 + (cq & 7) * 4,
              g_q + (size_t)(b * S_ + j0 + row) * DM_ + cq * 4);
    }
    #pragma unroll
    for (int r = 0; r < 8; r++) {
        int f = r * 256 + tid; int ii = f >> 8, j = (f >> 3) & 31, dq = f & 7;
        cpa16(sm + SC_OFF_R + ii * 1152 + j * 36 + dq * 4,
              rpe + ((size_t)(b * S_ + i0 + ii) * S_ + j0 + j) * D_ + dq * 4);
    }
    cpa_commit();

    // k rows for (i0+il, h) and (i0+il+4, h) in registers (overlaps staging)
    ull kp0[16], kp1[16];
    {
        const float* kg0 = g_k + (size_t)(b * S_ + i0 + il) * DM_ + h * 32;
        const float* kg1 = kg0 + (size_t)4 * DM_;
        #pragma unroll
        for (int t = 0; t < 8; t++) {
            float4 a = *(const float4*)(kg0 + t * 4);
            kp0[2 * t] = pack2(a.x, a.y); kp0[2 * t + 1] = pack2(a.z, a.w);
            float4 c = *(const float4*)(kg1 + t * 4);
            kp1[2 * t] = pack2(c.x, c.y); kp1[2 * t + 1] = pack2(c.z, c.w);
        }
    }
    cpa_wait<0>();
    __syncthreads();

    // warp w owns j = w*4 .. w*4+3 ; lane covers (il, h) x {i, i+4}
    float s0[4], s1[4];
    #pragma unroll
    for (int jj = 0; jj < 4; jj++) {
        const int j = w * 4 + jj;
        const float* qrow = sm + SC_OFF_Q + j * 292 + h * 36;
        const float* rp0  = sm + SC_OFF_R + il * 1152 + j * 36;
        const float* rp1  = rp0 + 4 * 1152;
        ull a0 = 0ull, a1 = 0ull;
        #pragma unroll
        for (int d4 = 0; d4 < 8; d4++) {
            ulonglong2 q2 = *(const ulonglong2*)(qrow + d4 * 4);
            ulonglong2 r0 = *(const ulonglong2*)(rp0 + d4 * 4);
            a0 = fma2(mul2(q2.x, kp0[2 * d4]),     r0.x, a0);
            a0 = fma2(mul2(q2.y, kp0[2 * d4 + 1]), r0.y, a0);
            ulonglong2 r1 = *(const ulonglong2*)(rp1 + d4 * 4);
            a1 = fma2(mul2(q2.x, kp1[2 * d4]),     r1.x, a1);
            a1 = fma2(mul2(q2.y, kp1[2 * d4 + 1]), r1.y, a1);
        }
        float2 t0 = unp2(a0), t1 = unp2(a1);
        s0[jj] = (t0.x + t0.y) * scale;
        s1[jj] = (t1.x + t1.y) * scale;
    }
    // store 4 j per (i,h) row: g_s[((b*S+i)*H+h)*S + j]
    const int jb = j0 + w * 4;
    float* r0 = g_s + ((size_t)(b * S_ + i0 + il)     * H_ + h) * S_ + jb;
    float* r1 = g_s + ((size_t)(b * S_ + i0 + il + 4) * H_ + h) * S_ + jb;
    if (jb + 3 < sn) {
        float4 o0; o0.x = s0[0]; o0.y = s0[1]; o0.z = s0[2]; o0.w = s0[3];
        float4 o1; o1.x = s1[0]; o1.y = s1[1]; o1.z = s1[2]; o1.w = s1[3];
        *(float4*)r0 = o0; *(float4*)r1 = o1;
    } else {
        #pragma unroll
        for (int jj = 0; jj < 4; jj++)
            if (jb + jj < sn) { r0[jj] = s0[jj]; r1[jj] = s1[jj]; }
    }
}

// ---------------------------------------------------------------------------
// Kernel 2b: softmax + AV. Block = (i-tile 8, b). 512 threads, grid 128.
// Stages scores [64 rows][<=256 j] + diag, softmax, then AV over v tiles.
// ---------------------------------------------------------------------------
constexpr int VJT = 32;
constexpr int SCS = 260;                              // sc row stride
constexpr int SV_OFF_SC = 0;                          // sc [64][260]
constexpr int SV_OFF_V  = 64 * SCS;                   // 16640 ; v 2x[32][292]
constexpr int SV_VBUF   = 32 * 292;                   // 9344
constexpr int SV_FLOATS = SV_OFF_V + 2 * SV_VBUF;     // 35328
constexpr int SV_BYTES  = SV_FLOATS * 4;              // 141,312 B

__global__ void __launch_bounds__(512, 1) sav_k(const float* __restrict__ rpe,
                                                const int* __restrict__ snp)
{
    extern __shared__ float sm[];
    float* sc = sm + SV_OFF_SC;
    const int tid = threadIdx.x;
    const int w = tid >> 5, lane = tid & 31;
    const int b = blockIdx.y, i0 = blockIdx.x * 8;
    int sn = *snp; if (sn > 256) sn = 256; if (sn < 0) sn = 0;
    const int nt = (sn + VJT - 1) / VJT;
    const float scale = 0.17677669529663687f;

    auto stage_v = [&](int t){
        int buf = t & 1, j0 = t * VJT;
        #pragma unroll
        for (int r = 0; r < 4; r++) {
            int f = r * 512 + tid; int row = f >> 6, cq = f & 63;
            cpa16(sm + SV_OFF_V + buf * SV_VBUF + row * 292 + (cq >> 3) * 36 + (cq & 7) * 4,
                  g_v + (size_t)(b * S_ + j0 + row) * DM_ + cq * 4);
        }
    };

    // stage scores: 64 rows (i*8+h) x nt*8 float4-chunks
    #pragma unroll
    for (int r = 0; r < 8; r++) {
        int f = r * 512 + tid; int row = f >> 6, cq = f & 63;
        if (cq < nt * 8)
            cpa16(sc + row * SCS + cq * 4,
                  g_s + ((size_t)(b * S_ + i0 + (row >> 3)) * H_ + (row & 7)) * S_ + cq * 4);
    }
    cpa_commit();                                   // group A (scores)
    if (nt > 0) stage_v(0);
    cpa_commit();                                   // group B (v0, maybe empty)
    if (nt > 1) stage_v(1);
    cpa_commit();                                   // group C (v1, maybe empty)

    // diagonal (rows i >= sn) computed from gmem — overlaps cp.async latency
    if (tid < 64) {
        int di = tid >> 3, dh = tid & 7;
        int ig = i0 + di;
        if (ig >= sn) {
            const float* qg = g_q + (size_t)(b * S_ + ig) * DM_ + dh * 32;
            const float* kg = g_k + (size_t)(b * S_ + ig) * DM_ + dh * 32;
            const float* rg = rpe + ((size_t)(b * S_ + ig) * S_ + ig) * D_;
            ull acc = 0ull;
            #pragma unroll
            for (int t = 0; t < 8; t++) {
                float4 qf = *(const float4*)(qg + t * 4);
                float4 kf = *(const float4*)(kg + t * 4);
                float4 rf = *(const float4*)(rg + t * 4);
                acc = fma2(mul2(pack2(qf.x, qf.y), pack2(kf.x, kf.y)), pack2(rf.x, rf.y), acc);
                acc = fma2(mul2(pack2(qf.z, qf.w), pack2(kf.z, kf.w)), pack2(rf.z, rf.w), acc);
            }
            float2 tt = unp2(acc);
            sc[(di * 8 + dh) * SCS + 256] = (tt.x + tt.y) * scale;
        }
    }
    cpa_wait<2>();                                  // scores complete
    __syncthreads();

    // softmax: 16 warps x 4 rows = 64 rows
    {
        const int jmax = nt * VJT;
        for (int rr = 0; rr < 4; rr++) {
            int row = w * 4 + rr;
            bool hd = (i0 + (row >> 3)) >= sn;
            float* srow = &sc[row * SCS];
            float mx = -1e30f;
            for (int jj = lane; jj < sn; jj += 32) mx = fmaxf(mx, srow[jj]);
            if (hd && lane == 0) mx = fmaxf(mx, srow[256]);
            #pragma unroll
            for (int o = 16; o > 0; o >>= 1) mx = fmaxf(mx, __shfl_xor_sync(0xffffffffu, mx, o));
            float sum = 0.f;
            for (int jj = lane; jj < jmax; jj += 32) {
                float p = (jj < sn) ? __expf(srow[jj] - mx) : 0.f;
                srow[jj] = p; sum += p;
            }
            if (hd && lane == 0) { float p = __expf(srow[256] - mx); srow[256] = p; sum += p; }
            #pragma unroll
            for (int o = 16; o > 0; o >>= 1) sum += __shfl_xor_sync(0xffffffffu, sum, o);
            float rn = 1.f / sum;
            for (int jj = lane; jj < jmax; jj += 32) srow[jj] *= rn;
            if (hd && lane == 0) srow[256] *= rn;
        }
    }

    // AV: thread owns (i = tid>>6, h = (tid>>3)&7, d-chunk = tid&7)
    const int ai = tid >> 6, h = (tid >> 3) & 7, dc = tid & 7;
    ull a0 = 0ull, a1 = 0ull;
    for (int t = 0; t < nt; t++) {
        if (t + 1 < nt) cpa_wait<1>(); else cpa_wait<0>();
        __syncthreads();
        const float* vb = sm + SV_OFF_V + (t & 1) * SV_VBUF;
        #pragma unroll
        for (int g = 0; g < 8; g++) {
            float4 p4 = *(const float4*)&sc[(ai * 8 + h) * SCS + t * VJT + g * 4];
            const float pv[4] = {p4.x, p4.y, p4.z, p4.w};
            #pragma unroll
            for (int jj = 0; jj < 4; jj++) {
                ulonglong2 v2 = *(const ulonglong2*)(vb + (g * 4 + jj) * 292 + h * 36 + dc * 4);
                ull pk = pack2(pv[jj], pv[jj]);
                a0 = fma2(pk, v2.x, a0);
                a1 = fma2(pk, v2.y, a1);
            }
        }
        __syncthreads();
        if (t + 2 < nt) { stage_v(t + 2); cpa_commit(); }
    }
    // diagonal term + store
    {
        int ig = i0 + ai;
        if (ig >= sn) {
            float p = sc[(ai * 8 + h) * SCS + 256];
            float4 vd = *(const float4*)(g_v + (size_t)(b * S_ + ig) * DM_ + h * 32 + dc * 4);
            ull pk = pack2(p, p);
            a0 = fma2(pk, pack2(vd.x, vd.y), a0);
            a1 = fma2(pk, pack2(vd.z, vd.w), a1);
        }
        float2 lo = unp2(a0), hi = unp2(a1);
        float4 o; o.x = lo.x; o.y = lo.y; o.z = hi.x; o.w = hi.y;
        *(float4*)(g_ao + (size_t)(b * S_ + ig) * DM_ + h * 32 + dc * 4) = o;
    }
}

// ---------------------------------------------------------------------------
// Kernel 3: epilogue. ctx = ao @ fc_w + fc_b + hs, then layernorm.
// Block = 8 rows x 256 cols; fc_w staged 32-k chunks, double-buffered.
// ---------------------------------------------------------------------------
constexpr int EOFF_AO  = 0;                      // 8 x 260
constexpr int EOFF_WS  = 2080;                   // 2 x 32 x 260
constexpr int EWS_BUF  = 32 * 260;
constexpr int EOFF_CTX = EOFF_WS + 2 * EWS_BUF;  // 8 x 260
constexpr int E_SMEM_FLOATS = EOFF_CTX + 8 * 260;
constexpr int E_SMEM_BYTES  = E_SMEM_FLOATS * 4; // 83,200 B

__global__ void __launch_bounds__(256) epi_k(const float* __restrict__ hs,
                                             const float* __restrict__ fw,
                                             const float* __restrict__ fb,
                                             const float* __restrict__ lw,
                                             const float* __restrict__ lb,
                                             float* __restrict__ out)
{
    extern __shared__ float es[];
    float* aos = es + EOFF_AO;
    float* ctx = es + EOFF_CTX;
    const int tid = threadIdx.x;
    const int cp = tid & 127, rh = tid >> 7;
    const int row0 = blockIdx.x * 8;

    auto stage_w = [&](int kt){
        int buf = kt & 1, k0 = kt * 32;
        #pragma unroll
        for (int r = 0; r < 8; r++) {
            int f = r * 256 + tid; int kr = f >> 6, cq = f & 63;
            cpa16(es + EOFF_WS + buf * EWS_BUF + kr * 260 + cq * 4,
                  fw + (size_t)(k0 + kr) * DM_ + cq * 4);
        }
    };
    #pragma unroll
    for (int r = 0; r < 2; r++) {
        int f = r * 256 + tid; int row = f >> 6, cq = f & 63;
        cpa16(aos + row * 260 + cq * 4, g_ao + (size_t)(row0 + row) * DM_ + cq * 4);
    }
    stage_w(0); cpa_commit();
    stage_w(1); cpa_commit();

    ull acc[4] = {0ull, 0ull, 0ull, 0ull};
    for (int kt = 0; kt < 8; kt++) {
        if (kt < 7) cpa_wait<1>(); else cpa_wait<0>();
        __syncthreads();
        const float* wb = es + EOFF_WS + (kt & 1) * EWS_BUF;
        const int k0 = kt * 32;
        #pragma unroll 8
        for (int kk = 0; kk < 32; kk++) {
            ull w2 = *(const ull*)(wb + kk * 260 + 2 * cp);
            #pragma unroll
            for (int r = 0; r < 4; r++) {
                float a = aos[(rh * 4 + r) * 260 + k0 + kk];
                acc[r] = fma2(pack2(a, a), w2, acc[r]);
            }
        }
        __syncthreads();
        if (kt + 2 < 8) { stage_w(kt + 2); cpa_commit(); }
    }

    const int cb = 2 * cp;
    float2 fb2 = *(const float2*)(fb + cb);
    #pragma unroll
    for (int r = 0; r < 4; r++) {
        int row = row0 + rh * 4 + r;
        float2 h2 = *(const float2*)(hs + (size_t)row * DM_ + cb);
        float2 t = unp2(acc[r]);
        t.x += fb2.x + h2.x; t.y += fb2.y + h2.y;
        *(float2*)(ctx + (rh * 4 + r) * 260 + cb) = t;
    }
    __syncthreads();

    {
        int w = tid >> 5, lane = tid & 31;
        float4 x0 = *(const float4*)(ctx + w * 260 + lane * 8);
        float4 x1 = *(const float4*)(ctx + w * 260 + lane * 8 + 4);
        float s = x0.x + x0.y + x0.z + x0.w + x1.x + x1.y + x1.z + x1.w;
        #pragma unroll
        for (int o = 16; o > 0; o >>= 1) s += __shfl_xor_sync(0xffffffffu, s, o);
        float mu = s * (1.f / 256.f);
        float v = 0.f;
        float xs[8] = {x0.x, x0.y, x0.z, x0.w, x1.x, x1.y, x1.z, x1.w};
        #pragma unroll
        for (int k = 0; k < 8; k++) { float d = xs[k] - mu; v += d * d; }
        #pragma unroll
        for (int o = 16; o > 0; o >>= 1) v += __shfl_xor_sync(0xffffffffu, v, o);
        float rs = rsqrtf(v * (1.f / 256.f) + 1e-6f);
        int c = lane * 8;
        float4 lw0 = *(const float4*)(lw + c), lw1 = *(const float4*)(lw + c + 4);
        float4 lb0 = *(const float4*)(lb + c), lb1 = *(const float4*)(lb + c + 4);
        float4 y0, y1;
        y0.x = (xs[0]-mu)*rs*lw0.x + lb0.x; y0.y = (xs[1]-mu)*rs*lw0.y + lb0.y;
        y0.z = (xs[2]-mu)*rs*lw0.z + lb0.z; y0.w = (xs[3]-mu)*rs*lw0.w + lb0.w;
        y1.x = (xs[4]-mu)*rs*lw1.x + lb1.x; y1.y = (xs[5]-mu)*rs*lw1.y + lb1.y;
        y1.z = (xs[6]-mu)*rs*lw1.z + lb1.z; y1.w = (xs[7]-mu)*rs*lw1.w + lb1.w;
        size_t ro = (size_t)(row0 + w) * DM_ + c;
        *(float4*)(out + ro)     = y0;
        *(float4*)(out + ro + 4) = y1;
    }
}

// ---------------------------------------------------------------------------
extern "C" void kernel_launch(void* const* d_in, const int* in_sizes, int n_in,
                              void* d_out, int out_size)
{
    const float* hs  = (const float*)d_in[0];
    const float* rpe = (const float*)d_in[1];
    const float* wq  = (const float*)d_in[2];
    const float* wk  = (const float*)d_in[3];
    const float* wv  = (const float*)d_in[4];
    const float* fw  = (const float*)d_in[5];
    const float* fb  = (const float*)d_in[6];
    const float* lw  = (const float*)d_in[7];
    const float* lb  = (const float*)d_in[8];
    const int*   sn  = (const int*)  d_in[9];
    float* out = (float*)d_out;

    cudaFuncSetAttribute(score_k, cudaFuncAttributeMaxDynamicSharedMemorySize, SC_BYTES);
    cudaFuncSetAttribute(sav_k,   cudaFuncAttributeMaxDynamicSharedMemorySize, SV_BYTES);
    cudaFuncSetAttribute(epi_k,   cudaFuncAttributeMaxDynamicSharedMemorySize, E_SMEM_BYTES);

    qkv_k<<<dim3(8, 16, 3), 128>>>(hs, wq, wk, wv);
    score_k<<<dim3(S_ / SJT, 64, 2), 256, SC_BYTES>>>(rpe, sn);
    sav_k<<<dim3(64, 2), 512, SV_BYTES>>>(rpe, sn);
    epi_k<<<128, 256, E_SMEM_BYTES>>>(hs, fw, fb, lw, lb, out);
}

// round 13
// speedup vs baseline: 1.1280x; 1.1280x over previous
#include <cuda_runtime.h>
#include <cstdint>
#include <cstddef>

typedef unsigned long long ull;
#define DI __device__ __forceinline__

DI ull pack2(float x, float y){ ull r; asm("mov.b64 %0,{%1,%2};":"=l"(r):"f"(x),"f"(y)); return r; }
DI float2 unp2(ull v){ float2 r; asm("mov.b64 {%0,%1},%2;":"=f"(r.x),"=f"(r.y):"l"(v)); return r; }
DI ull fma2(ull a, ull b, ull c){ ull d; asm("fma.rn.f32x2 %0,%1,%2,%3;":"=l"(d):"l"(a),"l"(b),"l"(c)); return d; }
DI ull mul2(ull a, ull b){ ull d; asm("mul.rn.f32x2 %0,%1,%2;":"=l"(d):"l"(a),"l"(b)); return d; }

DI void cpa16(void* dst_smem, const void* src_gmem){
    uint32_t s = (uint32_t)__cvta_generic_to_shared(dst_smem);
    asm volatile("cp.async.cg.shared.global [%0], [%1], 16;\n" :: "r"(s), "l"(src_gmem) : "memory");
}
DI void cpa_commit(){ asm volatile("cp.async.commit_group;\n" ::: "memory"); }
template<int N> DI void cpa_wait(){ asm volatile("cp.async.wait_group %0;\n" :: "n"(N) : "memory"); }

constexpr int B_ = 2, S_ = 512, H_ = 8, D_ = 32, DM_ = 256;
constexpr int M_ = B_ * S_;   // 1024 token rows

// Scratch (cudaMalloc forbidden)
__device__ float g_q [M_ * DM_];
__device__ float g_k [M_ * DM_];
__device__ float g_v [M_ * DM_];
__device__ float g_ao[M_ * DM_];
__device__ float g_cx[M_ * DM_];

// ---------------------------------------------------------------------------
// Kernel 1: QKV projections. out[m][n] = sum_k x[m][k] * w[k][n]
// 64x64 tiles, K-step 32, cp.async TRIPLE-buffered, 4x4 reg tile ping-pong.
// grid (4 n, 16 m, 3 mats), 256 threads. Dynamic smem (52 KB).
// ---------------------------------------------------------------------------
constexpr int QK_AS = 64 * 36;                       // per-buf A floats
constexpr int QK_BS = 32 * 64;                       // per-buf B floats
constexpr int QK_BS_OFF = 3 * QK_AS;                 // 6912
constexpr int QK_SMEM_FLOATS = 3 * QK_AS + 3 * QK_BS;  // 13056
constexpr int QK_SMEM_BYTES  = QK_SMEM_FLOATS * 4;     // 52,224 B

__global__ void __launch_bounds__(256) qkv_k(const float* __restrict__ x,
                                             const float* __restrict__ wq,
                                             const float* __restrict__ wk,
                                             const float* __restrict__ wv)
{
    extern __shared__ float smq[];
    const int bz = blockIdx.z;
    const float* w = (bz == 0) ? wq : ((bz == 1) ? wk : wv);
    float* out = (bz == 0) ? g_q : ((bz == 1) ? g_k : g_v);
    const int m0 = blockIdx.y * 64, n0 = blockIdx.x * 64;
    const int tid = threadIdx.x, tx = tid & 15, ty = tid >> 4;

    auto stage = [&](int kt){
        int buf = kt % 3, k0 = kt * 32;
        float* As = smq + buf * QK_AS;
        float* Bs = smq + QK_BS_OFF + buf * QK_BS;
        #pragma unroll
        for (int r = 0; r < 2; r++) {            // A: 64x32 = 512 chunks
            int f = r * 256 + tid; int row = f >> 3, kq = f & 7;
            cpa16(As + row * 36 + kq * 4, x + (size_t)(m0 + row) * DM_ + k0 + kq * 4);
        }
        #pragma unroll
        for (int r = 0; r < 2; r++) {            // B: 32x64 = 512 chunks
            int f = r * 256 + tid; int kk = f >> 4, nq = f & 15;
            cpa16(Bs + kk * 64 + nq * 4, w + (size_t)(k0 + kk) * DM_ + n0 + nq * 4);
        }
    };

    ull acc[4][2];
    #pragma unroll
    for (int r = 0; r < 4; r++) { acc[r][0] = 0ull; acc[r][1] = 0ull; }

    stage(0); cpa_commit();
    stage(1); cpa_commit();
    stage(2); cpa_commit();

    for (int kt = 0; kt < 8; kt++) {
        if (kt + 2 < 8) cpa_wait<2>(); else if (kt + 1 < 8) cpa_wait<1>(); else cpa_wait<0>();
        __syncthreads();
        const int buf = kt % 3;
        const float* As = smq + buf * QK_AS;
        const float* Bs = smq + QK_BS_OFF + buf * QK_BS;

        float4     aR[2][4];
        ulonglong2 bR[2][4];
        #pragma unroll
        for (int r = 0; r < 4; r++)
            aR[0][r] = *(const float4*)(As + (ty * 4 + r) * 36);
        #pragma unroll
        for (int kk = 0; kk < 4; kk++)
            bR[0][kk] = *(const ulonglong2*)(Bs + kk * 64 + tx * 4);

        #pragma unroll
        for (int k4 = 0; k4 < 8; k4++) {
            const int cur = k4 & 1, nxt = cur ^ 1;
            if (k4 < 7) {
                #pragma unroll
                for (int r = 0; r < 4; r++)
                    aR[nxt][r] = *(const float4*)(As + (ty * 4 + r) * 36 + (k4 + 1) * 4);
                #pragma unroll
                for (int kk = 0; kk < 4; kk++)
                    bR[nxt][kk] = *(const ulonglong2*)(Bs + ((k4 + 1) * 4 + kk) * 64 + tx * 4);
            }
            #pragma unroll
            for (int kk = 0; kk < 4; kk++) {
                #pragma unroll
                for (int r = 0; r < 4; r++) {
                    float a = ((const float*)&aR[cur][r])[kk];
                    ull ap = pack2(a, a);
                    acc[r][0] = fma2(ap, bR[cur][kk].x, acc[r][0]);
                    acc[r][1] = fma2(ap, bR[cur][kk].y, acc[r][1]);
                }
            }
        }
        __syncthreads();
        if (kt + 3 < 8) { stage(kt + 3); cpa_commit(); }
    }
    #pragma unroll
    for (int r = 0; r < 4; r++) {
        float2 lo = unp2(acc[r][0]), hi = unp2(acc[r][1]);
        float4 o; o.x = lo.x; o.y = lo.y; o.z = hi.x; o.w = hi.y;
        *(float4*)(out + (size_t)(m0 + ty * 4 + r) * DM_ + n0 + tx * 4) = o;
    }
}

// ---------------------------------------------------------------------------
// Kernel 2: attention. Block = (b, 8 query rows i, all 8 heads). 512 threads.
// Triple-buffered j-tiles of 16. Score: warp = j, lane = (il, h), two k rows
// in registers. AV: thread owns (i, h, 4-wide d-chunk). grid (64, 2).
// ---------------------------------------------------------------------------
constexpr int JT  = 16;
constexpr int QSB = JT * 292;                    // q/v buf: [j][h(36-pad)][d]
constexpr int RPB = 8 * 576;                     // rpe buf: [i(576)][j(36)][d]
constexpr int OFF_QS = 0;                        // 3 bufs
constexpr int OFF_RP = 3 * QSB;                  // 14016
constexpr int OFF_SC = OFF_RP + 3 * RPB;         // 27840 ; sc [64][260]
constexpr int SCS = 260;
constexpr int A_SMEM_FLOATS = OFF_SC + 64 * SCS; // 44480
constexpr int A_SMEM_BYTES  = A_SMEM_FLOATS * 4; // 177,920 B -> 1 CTA/SM

__global__ void __launch_bounds__(512, 1) attn_k(const float* __restrict__ rpe,
                                                 const int* __restrict__ snp)
{
    extern __shared__ float sm[];
    float* sc = sm + OFF_SC;
    const int tid = threadIdx.x;
    const int w = tid >> 5, lane = tid & 31;
    const int il = lane >> 3, h = lane & 7;
    const int b = blockIdx.y, i0 = blockIdx.x * 8;
    int sn = *snp; if (sn > 256) sn = 256; if (sn < 0) sn = 0;
    const int nt = (sn + JT - 1) / JT;
    const float scale = 0.17677669529663687f;     // 1/sqrt(32)

    // k rows for (il, h) and (il+4, h): 2 x 32 floats packed as f32x2
    ull kp0[16], kp1[16];
    {
        const float* kg0 = g_k + (size_t)(b * S_ + i0 + il) * DM_ + h * 32;
        const float* kg1 = kg0 + (size_t)4 * DM_;
        #pragma unroll
        for (int t = 0; t < 8; t++) {
            float4 a = *(const float4*)(kg0 + t * 4);
            kp0[2 * t] = pack2(a.x, a.y); kp0[2 * t + 1] = pack2(a.z, a.w);
            float4 c = *(const float4*)(kg1 + t * 4);
            kp1[2 * t] = pack2(c.x, c.y); kp1[2 * t + 1] = pack2(c.z, c.w);
        }
    }

    auto stage_qv = [&](const float* src_base, int t){    // 16 rows, head-padded
        int buf = t % 3, j0 = t * JT;
        #pragma unroll
        for (int r = 0; r < 2; r++) {
            int f = r * 512 + tid; int row = f >> 6, cq = f & 63;
            cpa16(sm + OFF_QS + buf * QSB + row * 292 + (cq >> 3) * 36 + (cq & 7) * 4,
                  src_base + (size_t)(b * S_ + j0 + row) * DM_ + cq * 4);
        }
    };
    auto stage_rpe = [&](int t){                          // 8 i x 16 j x 32 d
        int buf = t % 3, j0 = t * JT;
        #pragma unroll
        for (int r = 0; r < 2; r++) {
            int f = r * 512 + tid; int ii = f >> 7, j = (f >> 3) & 15, dq = f & 7;
            cpa16(sm + OFF_RP + buf * RPB + ii * 576 + j * 36 + dq * 4,
                  rpe + ((size_t)(b * S_ + i0 + ii) * S_ + j0 + j) * D_ + dq * 4);
        }
    };

    if (nt > 0) { stage_qv(g_q, 0); stage_rpe(0); cpa_commit(); }
    if (nt > 1) { stage_qv(g_q, 1); stage_rpe(1); cpa_commit(); }
    if (nt > 2) { stage_qv(g_q, 2); stage_rpe(2); cpa_commit(); }

    // ---------------- score phase: warp = j, lane = (il, h) ----------------
    for (int t = 0; t < nt; t++) {
        if (t + 2 < nt) cpa_wait<2>(); else if (t + 1 < nt) cpa_wait<1>(); else cpa_wait<0>();
        __syncthreads();
        const int buf = t % 3;
        const int jg = t * JT + w;
        const float* qrow = sm + OFF_QS + buf * QSB + w * 292 + h * 36;
        const float* rp0  = sm + OFF_RP + buf * RPB + il * 576 + w * 36;
        const float* rp1  = rp0 + 4 * 576;
        ull a0 = 0ull, a1 = 0ull;
        #pragma unroll
        for (int d4 = 0; d4 < 8; d4++) {
            ulonglong2 q2 = *(const ulonglong2*)(qrow + d4 * 4);
            ulonglong2 r0 = *(const ulonglong2*)(rp0 + d4 * 4);
            a0 = fma2(mul2(q2.x, kp0[2 * d4]),     r0.x, a0);
            a0 = fma2(mul2(q2.y, kp0[2 * d4 + 1]), r0.y, a0);
            ulonglong2 r1 = *(const ulonglong2*)(rp1 + d4 * 4);
            a1 = fma2(mul2(q2.x, kp1[2 * d4]),     r1.x, a1);
            a1 = fma2(mul2(q2.y, kp1[2 * d4 + 1]), r1.y, a1);
        }
        if (jg < sn) {
            float2 t0 = unp2(a0), t1 = unp2(a1);
            sc[(il * 8 + h) * SCS + jg]       = (t0.x + t0.y) * scale;
            sc[((il + 4) * 8 + h) * SCS + jg] = (t1.x + t1.y) * scale;
        }
        __syncthreads();
        if (t + 3 < nt) { stage_qv(g_q, t + 3); stage_rpe(t + 3); cpa_commit(); }
    }

    // prefetch v tiles 0..2 (overlaps diag + softmax)
    if (nt > 0) { stage_qv(g_v, 0); cpa_commit(); }
    if (nt > 1) { stage_qv(g_v, 1); cpa_commit(); }
    if (nt > 2) { stage_qv(g_v, 2); cpa_commit(); }

    // diagonal column (needed when row i0+i >= sn); operands from gmem/L2
    if (tid < 64) {
        int di = tid >> 3, dh = tid & 7;
        int ig = i0 + di;
        if (ig >= sn) {
            const float* qg = g_q + (size_t)(b * S_ + ig) * DM_ + dh * 32;
            const float* kg = g_k + (size_t)(b * S_ + ig) * DM_ + dh * 32;
            const float* rg = rpe + ((size_t)(b * S_ + ig) * S_ + ig) * D_;
            ull acc = 0ull;
            #pragma unroll
            for (int t = 0; t < 8; t++) {
                float4 qf = *(const float4*)(qg + t * 4);
                float4 kf = *(const float4*)(kg + t * 4);
                float4 rf = *(const float4*)(rg + t * 4);
                acc = fma2(mul2(pack2(qf.x, qf.y), pack2(kf.x, kf.y)), pack2(rf.x, rf.y), acc);
                acc = fma2(mul2(pack2(qf.z, qf.w), pack2(kf.z, kf.w)), pack2(rf.z, rf.w), acc);
            }
            float2 tt = unp2(acc);
            sc[(di * 8 + dh) * SCS + 256] = (tt.x + tt.y) * scale;
        }
    }
    __syncthreads();

    // ---------------- softmax (16 warps x 4 rows = 64 rows) ----------------
    {
        const int jmax = nt * JT;
        for (int rr = 0; rr < 4; rr++) {
            int row = w * 4 + rr;
            bool hd = (i0 + (row >> 3)) >= sn;
            float* srow = &sc[row * SCS];
            float mx = -1e30f;
            for (int jj = lane; jj < sn; jj += 32) mx = fmaxf(mx, srow[jj]);
            if (hd && lane == 0) mx = fmaxf(mx, srow[256]);
            #pragma unroll
            for (int o = 16; o > 0; o >>= 1) mx = fmaxf(mx, __shfl_xor_sync(0xffffffffu, mx, o));
            float sum = 0.f;
            for (int jj = lane; jj < jmax; jj += 32) {
                float p = (jj < sn) ? __expf(srow[jj] - mx) : 0.f;
                srow[jj] = p; sum += p;
            }
            if (hd && lane == 0) { float p = __expf(srow[256] - mx); srow[256] = p; sum += p; }
            #pragma unroll
            for (int o = 16; o > 0; o >>= 1) sum += __shfl_xor_sync(0xffffffffu, sum, o);
            float rn = 1.f / sum;
            for (int jj = lane; jj < jmax; jj += 32) srow[jj] *= rn;
            if (hd && lane == 0) srow[256] *= rn;
        }
    }

    // ------- AV phase: thread owns (i, h, 4-wide d-chunk) -------
    const int adc = w >> 1;                       // d-chunk 0..7
    const int ai  = il + 4 * (w & 1);             // i 0..7
    ull a0 = 0ull, a1 = 0ull;
    for (int t = 0; t < nt; t++) {
        if (t + 2 < nt) cpa_wait<2>(); else if (t + 1 < nt) cpa_wait<1>(); else cpa_wait<0>();
        __syncthreads();
        const float* vb = sm + OFF_QS + (t % 3) * QSB;
        #pragma unroll
        for (int g = 0; g < 4; g++) {
            float4 p4 = *(const float4*)&sc[(ai * 8 + h) * SCS + t * JT + g * 4];
            const float pv[4] = {p4.x, p4.y, p4.z, p4.w};
            #pragma unroll
            for (int jj = 0; jj < 4; jj++) {
                ulonglong2 v2 = *(const ulonglong2*)(vb + (g * 4 + jj) * 292 + h * 36 + adc * 4);
                ull pk = pack2(pv[jj], pv[jj]);
                a0 = fma2(pk, v2.x, a0);
                a1 = fma2(pk, v2.y, a1);
            }
        }
        __syncthreads();
        if (t + 3 < nt) { stage_qv(g_v, t + 3); cpa_commit(); }
    }
    // diagonal term + store
    {
        int ig = i0 + ai;
        if (ig >= sn) {
            float p = sc[(ai * 8 + h) * SCS + 256];
            float4 vd = *(const float4*)(g_v + (size_t)(b * S_ + ig) * DM_ + h * 32 + adc * 4);
            ull pk = pack2(p, p);
            a0 = fma2(pk, pack2(vd.x, vd.y), a0);
            a1 = fma2(pk, pack2(vd.z, vd.w), a1);
        }
        float2 lo = unp2(a0), hi = unp2(a1);
        float4 o; o.x = lo.x; o.y = lo.y; o.z = hi.x; o.w = hi.y;
        *(float4*)(g_ao + (size_t)(b * S_ + ig) * DM_ + h * 32 + adc * 4) = o;
    }
}

// ---------------------------------------------------------------------------
// Kernel 3a: epilogue GEMM. cx = ao @ fc_w + fc_b + hs (bias+residual fused).
// 32x32 tiles, 128 threads, grid (8 n, 32 m) = 256 blocks, depth-3.
// ---------------------------------------------------------------------------
__global__ void __launch_bounds__(128) epi_gemm_k(const float* __restrict__ hs,
                                                  const float* __restrict__ fw,
                                                  const float* __restrict__ fb)
{
    __shared__ float es[6 * 1152];    // 3 A bufs + 3 B bufs, each 32x36
    const int tid = threadIdx.x, tx = tid & 7, ty = tid >> 3;
    const int n0 = blockIdx.x * 32, m0 = blockIdx.y * 32;

    auto stage = [&](int kt){
        int buf = kt % 3, k0 = kt * 32;
        float* As = es + buf * 1152;
        float* Bs = es + 3 * 1152 + buf * 1152;
        #pragma unroll
        for (int r = 0; r < 2; r++) {            // A: 32x32 = 256 chunks
            int f = r * 128 + tid; int row = f >> 3, kq = f & 7;
            cpa16(As + row * 36 + kq * 4, g_ao + (size_t)(m0 + row) * DM_ + k0 + kq * 4);
        }
        #pragma unroll
        for (int r = 0; r < 2; r++) {            // B: 32x32 = 256 chunks
            int f = r * 128 + tid; int kk = f >> 3, nq = f & 7;
            cpa16(Bs + kk * 36 + nq * 4, fw + (size_t)(k0 + kk) * DM_ + n0 + nq * 4);
        }
    };

    ull acc[2][2];
    acc[0][0] = acc[0][1] = acc[1][0] = acc[1][1] = 0ull;

    stage(0); cpa_commit();
    stage(1); cpa_commit();
    stage(2); cpa_commit();

    for (int kt = 0; kt < 8; kt++) {
        if (kt + 2 < 8) cpa_wait<2>(); else if (kt + 1 < 8) cpa_wait<1>(); else cpa_wait<0>();
        __syncthreads();
        const float* As = es + (kt % 3) * 1152;
        const float* Bs = es + 3 * 1152 + (kt % 3) * 1152;
        #pragma unroll
        for (int k4 = 0; k4 < 8; k4++) {
            ulonglong2 bR[4];
            #pragma unroll
            for (int kk = 0; kk < 4; kk++)
                bR[kk] = *(const ulonglong2*)(Bs + (k4 * 4 + kk) * 36 + tx * 4);
            #pragma unroll
            for (int r = 0; r < 2; r++) {
                float4 a4 = *(const float4*)(As + (ty * 2 + r) * 36 + k4 * 4);
                acc[r][0] = fma2(pack2(a4.x, a4.x), bR[0].x, acc[r][0]);
                acc[r][1] = fma2(pack2(a4.x, a4.x), bR[0].y, acc[r][1]);
                acc[r][0] = fma2(pack2(a4.y, a4.y), bR[1].x, acc[r][0]);
                acc[r][1] = fma2(pack2(a4.y, a4.y), bR[1].y, acc[r][1]);
                acc[r][0] = fma2(pack2(a4.z, a4.z), bR[2].x, acc[r][0]);
                acc[r][1] = fma2(pack2(a4.z, a4.z), bR[2].y, acc[r][1]);
                acc[r][0] = fma2(pack2(a4.w, a4.w), bR[3].x, acc[r][0]);
                acc[r][1] = fma2(pack2(a4.w, a4.w), bR[3].y, acc[r][1]);
            }
        }
        __syncthreads();
        if (kt + 3 < 8) { stage(kt + 3); cpa_commit(); }
    }

    float4 fb4 = *(const float4*)(fb + n0 + tx * 4);
    #pragma unroll
    for (int r = 0; r < 2; r++) {
        int row = m0 + ty * 2 + r;
        float4 h4 = *(const float4*)(hs + (size_t)row * DM_ + n0 + tx * 4);
        float2 lo = unp2(acc[r][0]), hi = unp2(acc[r][1]);
        float4 o;
        o.x = lo.x + fb4.x + h4.x; o.y = lo.y + fb4.y + h4.y;
        o.z = hi.x + fb4.z + h4.z; o.w = hi.y + fb4.w + h4.w;
        *(float4*)(g_cx + (size_t)row * DM_ + n0 + tx * 4) = o;
    }
}

// ---------------------------------------------------------------------------
// Kernel 3b: layernorm. grid 256 x 128 thr; warp per row.
// ---------------------------------------------------------------------------
__global__ void __launch_bounds__(128) ln_k(const float* __restrict__ lw,
                                            const float* __restrict__ lb,
                                            float* __restrict__ out)
{
    const int tid = threadIdx.x, w = tid >> 5, lane = tid & 31;
    const int row = blockIdx.x * 4 + w;
    const float* xr = g_cx + (size_t)row * DM_ + lane * 8;
    float4 x0 = *(const float4*)xr;
    float4 x1 = *(const float4*)(xr + 4);
    float s = x0.x + x0.y + x0.z + x0.w + x1.x + x1.y + x1.z + x1.w;
    #pragma unroll
    for (int o = 16; o > 0; o >>= 1) s += __shfl_xor_sync(0xffffffffu, s, o);
    float mu = s * (1.f / 256.f);
    float xs[8] = {x0.x, x0.y, x0.z, x0.w, x1.x, x1.y, x1.z, x1.w};
    float v = 0.f;
    #pragma unroll
    for (int k = 0; k < 8; k++) { float d = xs[k] - mu; v += d * d; }
    #pragma unroll
    for (int o = 16; o > 0; o >>= 1) v += __shfl_xor_sync(0xffffffffu, v, o);
    float rs = rsqrtf(v * (1.f / 256.f) + 1e-6f);
    const int c = lane * 8;
    float4 lw0 = *(const float4*)(lw + c), lw1 = *(const float4*)(lw + c + 4);
    float4 lb0 = *(const float4*)(lb + c), lb1 = *(const float4*)(lb + c + 4);
    float4 y0, y1;
    y0.x = (xs[0]-mu)*rs*lw0.x + lb0.x; y0.y = (xs[1]-mu)*rs*lw0.y + lb0.y;
    y0.z = (xs[2]-mu)*rs*lw0.z + lb0.z; y0.w = (xs[3]-mu)*rs*lw0.w + lb0.w;
    y1.x = (xs[4]-mu)*rs*lw1.x + lb1.x; y1.y = (xs[5]-mu)*rs*lw1.y + lb1.y;
    y1.z = (xs[6]-mu)*rs*lw1.z + lb1.z; y1.w = (xs[7]-mu)*rs*lw1.w + lb1.w;
    size_t ro = (size_t)row * DM_ + c;
    *(float4*)(out + ro)     = y0;
    *(float4*)(out + ro + 4) = y1;
}

// ---------------------------------------------------------------------------
extern "C" void kernel_launch(void* const* d_in, const int* in_sizes, int n_in,
                              void* d_out, int out_size)
{
    const float* hs  = (const float*)d_in[0];
    const float* rpe = (const float*)d_in[1];
    const float* wq  = (const float*)d_in[2];
    const float* wk  = (const float*)d_in[3];
    const float* wv  = (const float*)d_in[4];
    const float* fw  = (const float*)d_in[5];
    const float* fb  = (const float*)d_in[6];
    const float* lw  = (const float*)d_in[7];
    const float* lb  = (const float*)d_in[8];
    const int*   sn  = (const int*)  d_in[9];
    float* out = (float*)d_out;

    cudaFuncSetAttribute(qkv_k,  cudaFuncAttributeMaxDynamicSharedMemorySize, QK_SMEM_BYTES);
    cudaFuncSetAttribute(attn_k, cudaFuncAttributeMaxDynamicSharedMemorySize, A_SMEM_BYTES);

    qkv_k<<<dim3(4, 16, 3), 256, QK_SMEM_BYTES>>>(hs, wq, wk, wv);
    attn_k<<<dim3(64, 2), 512, A_SMEM_BYTES>>>(rpe, sn);
    epi_gemm_k<<<dim3(8, 32), 128>>>(hs, fw, fb);
    ln_k<<<256, 128>>>(lw, lb, out);
}

// round 14
// speedup vs baseline: 1.2566x; 1.1141x over previous
#include <cuda_runtime.h>
#include <cstdint>
#include <cstddef>

typedef unsigned long long ull;
#define DI __device__ __forceinline__

DI ull pack2(float x, float y){ ull r; asm("mov.b64 %0,{%1,%2};":"=l"(r):"f"(x),"f"(y)); return r; }
DI float2 unp2(ull v){ float2 r; asm("mov.b64 {%0,%1},%2;":"=f"(r.x),"=f"(r.y):"l"(v)); return r; }
DI ull fma2(ull a, ull b, ull c){ ull d; asm("fma.rn.f32x2 %0,%1,%2,%3;":"=l"(d):"l"(a),"l"(b),"l"(c)); return d; }
DI ull mul2(ull a, ull b){ ull d; asm("mul.rn.f32x2 %0,%1,%2;":"=l"(d):"l"(a),"l"(b)); return d; }

DI void cpa16(void* dst_smem, const void* src_gmem){
    uint32_t s = (uint32_t)__cvta_generic_to_shared(dst_smem);
    asm volatile("cp.async.cg.shared.global [%0], [%1], 16;\n" :: "r"(s), "l"(src_gmem) : "memory");
}
DI void cpa_commit(){ asm volatile("cp.async.commit_group;\n" ::: "memory"); }
template<int N> DI void cpa_wait(){ asm volatile("cp.async.wait_group %0;\n" :: "n"(N) : "memory"); }

constexpr int B_ = 2, S_ = 512, H_ = 8, D_ = 32, DM_ = 256;
constexpr int M_ = B_ * S_;   // 1024 token rows

// Scratch (cudaMalloc forbidden)
__device__ float g_q [M_ * DM_];
__device__ float g_k [M_ * DM_];
__device__ float g_v [M_ * DM_];
__device__ float g_ao[M_ * DM_];
__device__ float g_cx[M_ * DM_];
__device__ unsigned g_bar;        // monotonic epoch counter (never reset)

// ---------------------------------------------------------------------------
// Kernel 1: QKV projections. out[m][n] = sum_k x[m][k] * w[k][n]
// 32x64 tiles, K-step 32, depth-3 cp.async, 4x4 reg tile ping-pong.
// grid (4 n, 32 m, 3 mats) = 384 blocks, 128 threads.
// ---------------------------------------------------------------------------
__global__ void __launch_bounds__(128) qkv_k(const float* __restrict__ x,
                                             const float* __restrict__ wq,
                                             const float* __restrict__ wk,
                                             const float* __restrict__ wv)
{
    __shared__ float As3[3][32 * 36];
    __shared__ float Bs3[3][32 * 64];
    const int bz = blockIdx.z;
    const float* w = (bz == 0) ? wq : ((bz == 1) ? wk : wv);
    float* out = (bz == 0) ? g_q : ((bz == 1) ? g_k : g_v);
    const int m0 = blockIdx.y * 32, n0 = blockIdx.x * 64;
    const int tid = threadIdx.x, tx = tid & 15, ty = tid >> 4;   // 16 cols x 8 rows groups

    auto stage = [&](int kt){
        int buf = kt % 3, k0 = kt * 32;
        float* As = As3[buf];
        float* Bs = Bs3[buf];
        #pragma unroll
        for (int r = 0; r < 2; r++) {            // A: 32x32 = 256 chunks
            int f = r * 128 + tid; int row = f >> 3, kq = f & 7;
            cpa16(As + row * 36 + kq * 4, x + (size_t)(m0 + row) * DM_ + k0 + kq * 4);
        }
        #pragma unroll
        for (int r = 0; r < 4; r++) {            // B: 32x64 = 512 chunks
            int f = r * 128 + tid; int kk = f >> 4, nq = f & 15;
            cpa16(Bs + kk * 64 + nq * 4, w + (size_t)(k0 + kk) * DM_ + n0 + nq * 4);
        }
    };

    ull acc[4][2];
    #pragma unroll
    for (int r = 0; r < 4; r++) { acc[r][0] = 0ull; acc[r][1] = 0ull; }

    stage(0); cpa_commit();
    stage(1); cpa_commit();
    stage(2); cpa_commit();

    for (int kt = 0; kt < 8; kt++) {
        if (kt + 2 < 8) cpa_wait<2>(); else if (kt + 1 < 8) cpa_wait<1>(); else cpa_wait<0>();
        __syncthreads();
        const float* As = As3[kt % 3];
        const float* Bs = Bs3[kt % 3];

        float4     aR[2][4];
        ulonglong2 bR[2][4];
        #pragma unroll
        for (int r = 0; r < 4; r++)
            aR[0][r] = *(const float4*)(As + (ty * 4 + r) * 36);
        #pragma unroll
        for (int kk = 0; kk < 4; kk++)
            bR[0][kk] = *(const ulonglong2*)(Bs + kk * 64 + tx * 4);

        #pragma unroll
        for (int k4 = 0; k4 < 8; k4++) {
            const int cur = k4 & 1, nxt = cur ^ 1;
            if (k4 < 7) {
                #pragma unroll
                for (int r = 0; r < 4; r++)
                    aR[nxt][r] = *(const float4*)(As + (ty * 4 + r) * 36 + (k4 + 1) * 4);
                #pragma unroll
                for (int kk = 0; kk < 4; kk++)
                    bR[nxt][kk] = *(const ulonglong2*)(Bs + ((k4 + 1) * 4 + kk) * 64 + tx * 4);
            }
            #pragma unroll
            for (int kk = 0; kk < 4; kk++) {
                #pragma unroll
                for (int r = 0; r < 4; r++) {
                    float a = ((const float*)&aR[cur][r])[kk];
                    ull ap = pack2(a, a);
                    acc[r][0] = fma2(ap, bR[cur][kk].x, acc[r][0]);
                    acc[r][1] = fma2(ap, bR[cur][kk].y, acc[r][1]);
                }
            }
        }
        __syncthreads();
        if (kt + 3 < 8) { stage(kt + 3); cpa_commit(); }
    }
    #pragma unroll
    for (int r = 0; r < 4; r++) {
        float2 lo = unp2(acc[r][0]), hi = unp2(acc[r][1]);
        float4 o; o.x = lo.x; o.y = lo.y; o.z = hi.x; o.w = hi.y;
        *(float4*)(out + (size_t)(m0 + ty * 4 + r) * DM_ + n0 + tx * 4) = o;
    }
}

// ---------------------------------------------------------------------------
// Kernel 2: attention. Block = (b, 8 query rows i, all 8 heads). 512 threads.
// j-tiles of 32, depth-2. Score: warp owns j = {w, w+16}; lane = (il, h),
// two register k rows. AV: thread owns (i, h, 4-wide d-chunk). grid (64, 2).
// rpe i-stride 1156 (pad) -> conflict-free LDS.
// ---------------------------------------------------------------------------
constexpr int JT  = 32;
constexpr int QSB = JT * 292;                    // q/v buf: [j][h(36-pad)][d] = 9344
constexpr int RPB = 8 * 1156;                    // rpe buf: [i(1156)][j(36)][d] = 9248
constexpr int OFF_QS = 0;                        // 2 bufs
constexpr int OFF_RP = 2 * QSB;                  // 18688
constexpr int OFF_SC = OFF_RP + 2 * RPB;         // 37184 ; sc [64][260]
constexpr int SCS = 260;
constexpr int A_SMEM_FLOATS = OFF_SC + 64 * SCS; // 53824
constexpr int A_SMEM_BYTES  = A_SMEM_FLOATS * 4; // 215,296 B -> 1 CTA/SM

__global__ void __launch_bounds__(512, 1) attn_k(const float* __restrict__ rpe,
                                                 const int* __restrict__ snp)
{
    extern __shared__ float sm[];
    float* sc = sm + OFF_SC;
    const int tid = threadIdx.x;
    const int w = tid >> 5, lane = tid & 31;
    const int il = lane >> 3, h = lane & 7;
    const int b = blockIdx.y, i0 = blockIdx.x * 8;
    int sn = *snp; if (sn > 256) sn = 256; if (sn < 0) sn = 0;
    const int nt = (sn + JT - 1) / JT;            // <= 8
    const float scale = 0.17677669529663687f;     // 1/sqrt(32)

    // k rows for (il, h) and (il+4, h): 2 x 32 floats packed as f32x2
    ull kp0[16], kp1[16];
    {
        const float* kg0 = g_k + (size_t)(b * S_ + i0 + il) * DM_ + h * 32;
        const float* kg1 = kg0 + (size_t)4 * DM_;
        #pragma unroll
        for (int t = 0; t < 8; t++) {
            float4 a = *(const float4*)(kg0 + t * 4);
            kp0[2 * t] = pack2(a.x, a.y); kp0[2 * t + 1] = pack2(a.z, a.w);
            float4 c = *(const float4*)(kg1 + t * 4);
            kp1[2 * t] = pack2(c.x, c.y); kp1[2 * t + 1] = pack2(c.z, c.w);
        }
    }

    auto stage_qv = [&](const float* src_base, int t){    // 32 rows, head-padded
        int buf = t & 1, j0 = t * JT;
        #pragma unroll
        for (int r = 0; r < 4; r++) {
            int f = r * 512 + tid; int row = f >> 6, cq = f & 63;
            cpa16(sm + OFF_QS + buf * QSB + row * 292 + (cq >> 3) * 36 + (cq & 7) * 4,
                  src_base + (size_t)(b * S_ + j0 + row) * DM_ + cq * 4);
        }
    };
    auto stage_rpe = [&](int t){                          // 8 i x 32 j x 32 d
        int buf = t & 1, j0 = t * JT;
        #pragma unroll
        for (int r = 0; r < 4; r++) {
            int f = r * 512 + tid; int ii = f >> 8, j = (f >> 3) & 31, dq = f & 7;
            cpa16(sm + OFF_RP + buf * RPB + ii * 1156 + j * 36 + dq * 4,
                  rpe + ((size_t)(b * S_ + i0 + ii) * S_ + j0 + j) * D_ + dq * 4);
        }
    };

    if (nt > 0) { stage_qv(g_q, 0); stage_rpe(0); cpa_commit(); }
    if (nt > 1) { stage_qv(g_q, 1); stage_rpe(1); cpa_commit(); }

    // ---------------- score phase: warp covers j = {w, w+16} ----------------
    for (int t = 0; t < nt; t++) {
        if (t + 1 < nt) cpa_wait<1>(); else cpa_wait<0>();
        __syncthreads();
        const int buf = t & 1;
        #pragma unroll
        for (int jj = 0; jj < 2; jj++) {
            const int j = w + jj * 16, jg = t * JT + j;
            const float* qrow = sm + OFF_QS + buf * QSB + j * 292 + h * 36;
            const float* rp0  = sm + OFF_RP + buf * RPB + il * 1156 + j * 36;
            const float* rp1  = rp0 + 4 * 1156;
            ull a0 = 0ull, a1 = 0ull;
            #pragma unroll
            for (int d4 = 0; d4 < 8; d4++) {
                ulonglong2 q2 = *(const ulonglong2*)(qrow + d4 * 4);
                ulonglong2 r0 = *(const ulonglong2*)(rp0 + d4 * 4);
                a0 = fma2(mul2(q2.x, kp0[2 * d4]),     r0.x, a0);
                a0 = fma2(mul2(q2.y, kp0[2 * d4 + 1]), r0.y, a0);
                ulonglong2 r1 = *(const ulonglong2*)(rp1 + d4 * 4);
                a1 = fma2(mul2(q2.x, kp1[2 * d4]),     r1.x, a1);
                a1 = fma2(mul2(q2.y, kp1[2 * d4 + 1]), r1.y, a1);
            }
            if (jg < sn) {
                float2 t0 = unp2(a0), t1 = unp2(a1);
                sc[(il * 8 + h) * SCS + jg]       = (t0.x + t0.y) * scale;
                sc[((il + 4) * 8 + h) * SCS + jg] = (t1.x + t1.y) * scale;
            }
        }
        __syncthreads();
        if (t + 2 < nt) { stage_qv(g_q, t + 2); stage_rpe(t + 2); cpa_commit(); }
    }

    // prefetch v tiles 0,1 (overlaps diag + softmax)
    if (nt > 0) { stage_qv(g_v, 0); cpa_commit(); }
    if (nt > 1) { stage_qv(g_v, 1); cpa_commit(); }

    // diagonal column (needed when row i0+i >= sn); operands from gmem/L2
    if (tid < 64) {
        int di = tid >> 3, dh = tid & 7;
        int ig = i0 + di;
        if (ig >= sn) {
            const float* qg = g_q + (size_t)(b * S_ + ig) * DM_ + dh * 32;
            const float* kg = g_k + (size_t)(b * S_ + ig) * DM_ + dh * 32;
            const float* rg = rpe + ((size_t)(b * S_ + ig) * S_ + ig) * D_;
            ull acc = 0ull;
            #pragma unroll
            for (int t = 0; t < 8; t++) {
                float4 qf = *(const float4*)(qg + t * 4);
                float4 kf = *(const float4*)(kg + t * 4);
                float4 rf = *(const float4*)(rg + t * 4);
                acc = fma2(mul2(pack2(qf.x, qf.y), pack2(kf.x, kf.y)), pack2(rf.x, rf.y), acc);
                acc = fma2(mul2(pack2(qf.z, qf.w), pack2(kf.z, kf.w)), pack2(rf.z, rf.w), acc);
            }
            float2 tt = unp2(acc);
            sc[(di * 8 + dh) * SCS + 256] = (tt.x + tt.y) * scale;
        }
    }
    __syncthreads();

    // ---------------- softmax (16 warps x 4 rows = 64 rows) ----------------
    {
        const int jmax = nt * JT;
        for (int rr = 0; rr < 4; rr++) {
            int row = w * 4 + rr;
            bool hd = (i0 + (row >> 3)) >= sn;
            float* srow = &sc[row * SCS];
            float mx = -1e30f;
            for (int jj = lane; jj < sn; jj += 32) mx = fmaxf(mx, srow[jj]);
            if (hd && lane == 0) mx = fmaxf(mx, srow[256]);
            #pragma unroll
            for (int o = 16; o > 0; o >>= 1) mx = fmaxf(mx, __shfl_xor_sync(0xffffffffu, mx, o));
            float sum = 0.f;
            for (int jj = lane; jj < jmax; jj += 32) {
                float p = (jj < sn) ? __expf(srow[jj] - mx) : 0.f;
                srow[jj] = p; sum += p;
            }
            if (hd && lane == 0) { float p = __expf(srow[256] - mx); srow[256] = p; sum += p; }
            #pragma unroll
            for (int o = 16; o > 0; o >>= 1) sum += __shfl_xor_sync(0xffffffffu, sum, o);
            float rn = 1.f / sum;
            for (int jj = lane; jj < jmax; jj += 32) srow[jj] *= rn;
            if (hd && lane == 0) srow[256] *= rn;
        }
    }

    // ------- AV phase: thread owns (i = tid>>6, h = (tid>>3)&7, dc = tid&7) -
    const int ai = tid >> 6, ah = (tid >> 3) & 7, dc = tid & 7;
    ull a0 = 0ull, a1 = 0ull;
    for (int t = 0; t < nt; t++) {
        if (t + 1 < nt) cpa_wait<1>(); else cpa_wait<0>();
        __syncthreads();
        const float* vb = sm + OFF_QS + (t & 1) * QSB;
        #pragma unroll
        for (int g = 0; g < 8; g++) {
            float4 p4 = *(const float4*)&sc[(ai * 8 + ah) * SCS + t * JT + g * 4];
            const float pv[4] = {p4.x, p4.y, p4.z, p4.w};
            #pragma unroll
            for (int jj = 0; jj < 4; jj++) {
                ulonglong2 v2 = *(const ulonglong2*)(vb + (g * 4 + jj) * 292 + ah * 36 + dc * 4);
                ull pk = pack2(pv[jj], pv[jj]);
                a0 = fma2(pk, v2.x, a0);
                a1 = fma2(pk, v2.y, a1);
            }
        }
        __syncthreads();
        if (t + 2 < nt) { stage_qv(g_v, t + 2); cpa_commit(); }
    }
    // diagonal term + store
    {
        int ig = i0 + ai;
        if (ig >= sn) {
            float p = sc[(ai * 8 + ah) * SCS + 256];
            float4 vd = *(const float4*)(g_v + (size_t)(b * S_ + ig) * DM_ + ah * 32 + dc * 4);
            ull pk = pack2(p, p);
            a0 = fma2(pk, pack2(vd.x, vd.y), a0);
            a1 = fma2(pk, pack2(vd.z, vd.w), a1);
        }
        float2 lo = unp2(a0), hi = unp2(a1);
        float4 o; o.x = lo.x; o.y = lo.y; o.z = hi.x; o.w = hi.y;
        *(float4*)(g_ao + (size_t)(b * S_ + ig) * DM_ + ah * 32 + dc * 4) = o;
    }
}

// ---------------------------------------------------------------------------
// Kernel 3: epilogue GEMM + global barrier + layernorm (one kernel).
// GEMM: 32x32 tiles, 128 threads, grid (8 n, 32 m) = 256 blocks, depth-3.
// Then epoch flag-barrier (all 256 blocks resident: 128 thr, 27KB smem ->
// >=2 CTAs/SM so no deadlock), then each block layernorms 4 rows.
// ---------------------------------------------------------------------------
__global__ void __launch_bounds__(128) epi_k(const float* __restrict__ hs,
                                             const float* __restrict__ fw,
                                             const float* __restrict__ fb,
                                             const float* __restrict__ lw,
                                             const float* __restrict__ lb,
                                             float* __restrict__ out)
{
    __shared__ float es[6 * 1152];    // 3 A bufs + 3 B bufs, each 32x36
    const int tid = threadIdx.x, tx = tid & 7, ty = tid >> 3;
    const int n0 = blockIdx.x * 32, m0 = blockIdx.y * 32;

    auto stage = [&](int kt){
        int buf = kt % 3, k0 = kt * 32;
        float* As = es + buf * 1152;
        float* Bs = es + 3 * 1152 + buf * 1152;
        #pragma unroll
        for (int r = 0; r < 2; r++) {            // A: 32x32 = 256 chunks
            int f = r * 128 + tid; int row = f >> 3, kq = f & 7;
            cpa16(As + row * 36 + kq * 4, g_ao + (size_t)(m0 + row) * DM_ + k0 + kq * 4);
        }
        #pragma unroll
        for (int r = 0; r < 2; r++) {            // B: 32x32 = 256 chunks
            int f = r * 128 + tid; int kk = f >> 3, nq = f & 7;
            cpa16(Bs + kk * 36 + nq * 4, fw + (size_t)(k0 + kk) * DM_ + n0 + nq * 4);
        }
    };

    ull acc[2][2];
    acc[0][0] = acc[0][1] = acc[1][0] = acc[1][1] = 0ull;

    stage(0); cpa_commit();
    stage(1); cpa_commit();
    stage(2); cpa_commit();

    for (int kt = 0; kt < 8; kt++) {
        if (kt + 2 < 8) cpa_wait<2>(); else if (kt + 1 < 8) cpa_wait<1>(); else cpa_wait<0>();
        __syncthreads();
        const float* As = es + (kt % 3) * 1152;
        const float* Bs = es + 3 * 1152 + (kt % 3) * 1152;
        #pragma unroll
        for (int k4 = 0; k4 < 8; k4++) {
            ulonglong2 bR[4];
            #pragma unroll
            for (int kk = 0; kk < 4; kk++)
                bR[kk] = *(const ulonglong2*)(Bs + (k4 * 4 + kk) * 36 + tx * 4);
            #pragma unroll
            for (int r = 0; r < 2; r++) {
                float4 a4 = *(const float4*)(As + (ty * 2 + r) * 36 + k4 * 4);
                acc[r][0] = fma2(pack2(a4.x, a4.x), bR[0].x, acc[r][0]);
                acc[r][1] = fma2(pack2(a4.x, a4.x), bR[0].y, acc[r][1]);
                acc[r][0] = fma2(pack2(a4.y, a4.y), bR[1].x, acc[r][0]);
                acc[r][1] = fma2(pack2(a4.y, a4.y), bR[1].y, acc[r][1]);
                acc[r][0] = fma2(pack2(a4.z, a4.z), bR[2].x, acc[r][0]);
                acc[r][1] = fma2(pack2(a4.z, a4.z), bR[2].y, acc[r][1]);
                acc[r][0] = fma2(pack2(a4.w, a4.w), bR[3].x, acc[r][0]);
                acc[r][1] = fma2(pack2(a4.w, a4.w), bR[3].y, acc[r][1]);
            }
        }
        __syncthreads();
        if (kt + 3 < 8) { stage(kt + 3); cpa_commit(); }
    }

    // bias + residual -> g_cx
    float4 fb4 = *(const float4*)(fb + n0 + tx * 4);
    #pragma unroll
    for (int r = 0; r < 2; r++) {
        int row = m0 + ty * 2 + r;
        float4 h4 = *(const float4*)(hs + (size_t)row * DM_ + n0 + tx * 4);
        float2 lo = unp2(acc[r][0]), hi = unp2(acc[r][1]);
        float4 o;
        o.x = lo.x + fb4.x + h4.x; o.y = lo.y + fb4.y + h4.y;
        o.z = hi.x + fb4.z + h4.z; o.w = hi.y + fb4.w + h4.w;
        *(float4*)(g_cx + (size_t)row * DM_ + n0 + tx * 4) = o;
    }

    // ---- global flag barrier (epoch-based; monotonic, no reset needed) ----
    __threadfence();
    if (tid == 0) {
        unsigned old = atomicAdd(&g_bar, 1u);
        unsigned tgt = ((old >> 8) + 1u) << 8;           // (old/256+1)*256
        volatile unsigned* p = &g_bar;
        while (*p < tgt) { }
    }
    __syncthreads();
    __threadfence();

    // ---- layernorm: this block handles 4 rows (warp per row) ----
    {
        const int bid = blockIdx.y * 8 + blockIdx.x;     // 0..255
        const int w = tid >> 5, lane = tid & 31;
        const int row = bid * 4 + w;
        const float* xr = g_cx + (size_t)row * DM_ + lane * 8;
        float4 x0 = *(const float4*)xr;
        float4 x1 = *(const float4*)(xr + 4);
        float s = x0.x + x0.y + x0.z + x0.w + x1.x + x1.y + x1.z + x1.w;
        #pragma unroll
        for (int o = 16; o > 0; o >>= 1) s += __shfl_xor_sync(0xffffffffu, s, o);
        float mu = s * (1.f / 256.f);
        float xs[8] = {x0.x, x0.y, x0.z, x0.w, x1.x, x1.y, x1.z, x1.w};
        float v = 0.f;
        #pragma unroll
        for (int k = 0; k < 8; k++) { float d = xs[k] - mu; v += d * d; }
        #pragma unroll
        for (int o = 16; o > 0; o >>= 1) v += __shfl_xor_sync(0xffffffffu, v, o);
        float rs = rsqrtf(v * (1.f / 256.f) + 1e-6f);
        const int c = lane * 8;
        float4 lw0 = *(const float4*)(lw + c), lw1 = *(const float4*)(lw + c + 4);
        float4 lb0 = *(const float4*)(lb + c), lb1 = *(const float4*)(lb + c + 4);
        float4 y0, y1;
        y0.x = (xs[0]-mu)*rs*lw0.x + lb0.x; y0.y = (xs[1]-mu)*rs*lw0.y + lb0.y;
        y0.z = (xs[2]-mu)*rs*lw0.z + lb0.z; y0.w = (xs[3]-mu)*rs*lw0.w + lb0.w;
        y1.x = (xs[4]-mu)*rs*lw1.x + lb1.x; y1.y = (xs[5]-mu)*rs*lw1.y + lb1.y;
        y1.z = (xs[6]-mu)*rs*lw1.z + lb1.z; y1.w = (xs[7]-mu)*rs*lw1.w + lb1.w;
        size_t ro = (size_t)row * DM_ + c;
        *(float4*)(out + ro)     = y0;
        *(float4*)(out + ro + 4) = y1;
    }
}

// ---------------------------------------------------------------------------
extern "C" void kernel_launch(void* const* d_in, const int* in_sizes, int n_in,
                              void* d_out, int out_size)
{
    const float* hs  = (const float*)d_in[0];
    const float* rpe = (const float*)d_in[1];
    const float* wq  = (const float*)d_in[2];
    const float* wk  = (const float*)d_in[3];
    const float* wv  = (const float*)d_in[4];
    const float* fw  = (const float*)d_in[5];
    const float* fb  = (const float*)d_in[6];
    const float* lw  = (const float*)d_in[7];
    const float* lb  = (const float*)d_in[8];
    const int*   sn  = (const int*)  d_in[9];
    float* out = (float*)d_out;

    cudaFuncSetAttribute(attn_k, cudaFuncAttributeMaxDynamicSharedMemorySize, A_SMEM_BYTES);

    qkv_k<<<dim3(4, 32, 3), 128>>>(hs, wq, wk, wv);
    attn_k<<<dim3(64, 2), 512, A_SMEM_BYTES>>>(rpe, sn);
    epi_k<<<dim3(8, 32), 128>>>(hs, fw, fb, lw, lb, out);
}

// round 15
// speedup vs baseline: 1.2579x; 1.0010x over previous
#include <cuda_runtime.h>
#include <cstdint>
#include <cstddef>

typedef unsigned long long ull;
#define DI __device__ __forceinline__

DI ull pack2(float x, float y){ ull r; asm("mov.b64 %0,{%1,%2};":"=l"(r):"f"(x),"f"(y)); return r; }
DI float2 unp2(ull v){ float2 r; asm("mov.b64 {%0,%1},%2;":"=f"(r.x),"=f"(r.y):"l"(v)); return r; }
DI ull fma2(ull a, ull b, ull c){ ull d; asm("fma.rn.f32x2 %0,%1,%2,%3;":"=l"(d):"l"(a),"l"(b),"l"(c)); return d; }
DI ull mul2(ull a, ull b){ ull d; asm("mul.rn.f32x2 %0,%1,%2;":"=l"(d):"l"(a),"l"(b)); return d; }

DI void cpa16(void* dst_smem, const void* src_gmem){
    uint32_t s = (uint32_t)__cvta_generic_to_shared(dst_smem);
    asm volatile("cp.async.cg.shared.global [%0], [%1], 16;\n" :: "r"(s), "l"(src_gmem) : "memory");
}
DI void cpa_commit(){ asm volatile("cp.async.commit_group;\n" ::: "memory"); }
template<int N> DI void cpa_wait(){ asm volatile("cp.async.wait_group %0;\n" :: "n"(N) : "memory"); }

constexpr int B_ = 2, S_ = 512, H_ = 8, D_ = 32, DM_ = 256;
constexpr int M_ = B_ * S_;   // 1024 token rows

// Scratch (cudaMalloc forbidden)
__device__ float g_q [M_ * DM_];
__device__ float g_k [M_ * DM_];
__device__ float g_v [M_ * DM_];
__device__ float g_ao[M_ * DM_];
__device__ float g_cx[M_ * DM_];
__device__ unsigned g_bar;        // monotonic epoch counter (never reset)

// ---------------------------------------------------------------------------
// Kernel 1: QKV projections. out[m][n] = sum_k x[m][k] * w[k][n]
// 32x64 tiles, K-step 32, depth-3 cp.async, 4x4 reg tile ping-pong.
// grid (4 n, 32 m, 3 mats) = 384 blocks, 128 threads.
// ---------------------------------------------------------------------------
__global__ void __launch_bounds__(128) qkv_k(const float* __restrict__ x,
                                             const float* __restrict__ wq,
                                             const float* __restrict__ wk,
                                             const float* __restrict__ wv)
{
    __shared__ float As3[3][32 * 36];
    __shared__ float Bs3[3][32 * 64];
    const int bz = blockIdx.z;
    const float* w = (bz == 0) ? wq : ((bz == 1) ? wk : wv);
    float* out = (bz == 0) ? g_q : ((bz == 1) ? g_k : g_v);
    const int m0 = blockIdx.y * 32, n0 = blockIdx.x * 64;
    const int tid = threadIdx.x, tx = tid & 15, ty = tid >> 4;   // 16 cols x 8 rows groups

    auto stage = [&](int kt){
        int buf = kt % 3, k0 = kt * 32;
        float* As = As3[buf];
        float* Bs = Bs3[buf];
        #pragma unroll
        for (int r = 0; r < 2; r++) {            // A: 32x32 = 256 chunks
            int f = r * 128 + tid; int row = f >> 3, kq = f & 7;
            cpa16(As + row * 36 + kq * 4, x + (size_t)(m0 + row) * DM_ + k0 + kq * 4);
        }
        #pragma unroll
        for (int r = 0; r < 4; r++) {            // B: 32x64 = 512 chunks
            int f = r * 128 + tid; int kk = f >> 4, nq = f & 15;
            cpa16(Bs + kk * 64 + nq * 4, w + (size_t)(k0 + kk) * DM_ + n0 + nq * 4);
        }
    };

    ull acc[4][2];
    #pragma unroll
    for (int r = 0; r < 4; r++) { acc[r][0] = 0ull; acc[r][1] = 0ull; }

    stage(0); cpa_commit();
    stage(1); cpa_commit();
    stage(2); cpa_commit();

    for (int kt = 0; kt < 8; kt++) {
        if (kt + 2 < 8) cpa_wait<2>(); else if (kt + 1 < 8) cpa_wait<1>(); else cpa_wait<0>();
        __syncthreads();
        const float* As = As3[kt % 3];
        const float* Bs = Bs3[kt % 3];

        float4     aR[2][4];
        ulonglong2 bR[2][4];
        #pragma unroll
        for (int r = 0; r < 4; r++)
            aR[0][r] = *(const float4*)(As + (ty * 4 + r) * 36);
        #pragma unroll
        for (int kk = 0; kk < 4; kk++)
            bR[0][kk] = *(const ulonglong2*)(Bs + kk * 64 + tx * 4);

        #pragma unroll
        for (int k4 = 0; k4 < 8; k4++) {
            const int cur = k4 & 1, nxt = cur ^ 1;
            if (k4 < 7) {
                #pragma unroll
                for (int r = 0; r < 4; r++)
                    aR[nxt][r] = *(const float4*)(As + (ty * 4 + r) * 36 + (k4 + 1) * 4);
                #pragma unroll
                for (int kk = 0; kk < 4; kk++)
                    bR[nxt][kk] = *(const ulonglong2*)(Bs + ((k4 + 1) * 4 + kk) * 64 + tx * 4);
            }
            #pragma unroll
            for (int kk = 0; kk < 4; kk++) {
                #pragma unroll
                for (int r = 0; r < 4; r++) {
                    float a = ((const float*)&aR[cur][r])[kk];
                    ull ap = pack2(a, a);
                    acc[r][0] = fma2(ap, bR[cur][kk].x, acc[r][0]);
                    acc[r][1] = fma2(ap, bR[cur][kk].y, acc[r][1]);
                }
            }
        }
        __syncthreads();
        if (kt + 3 < 8) { stage(kt + 3); cpa_commit(); }
    }
    #pragma unroll
    for (int r = 0; r < 4; r++) {
        float2 lo = unp2(acc[r][0]), hi = unp2(acc[r][1]);
        float4 o; o.x = lo.x; o.y = lo.y; o.z = hi.x; o.w = hi.y;
        *(float4*)(out + (size_t)(m0 + ty * 4 + r) * DM_ + n0 + tx * 4) = o;
    }
}

// ---------------------------------------------------------------------------
// Kernel 2: attention. Block = (b, 8 query rows i, all 8 heads). 512 threads.
// j-tiles of 32, depth-2. Score: warp owns j = {w, w+16}; lane = (il, h),
// two register k rows. AV: thread owns (i, h, 4-wide d-chunk). grid (64, 2).
// rpe i-stride 1156 (pad) -> conflict-free LDS.
// ---------------------------------------------------------------------------
constexpr int JT  = 32;
constexpr int QSB = JT * 292;                    // q/v buf: [j][h(36-pad)][d] = 9344
constexpr int RPB = 8 * 1156;                    // rpe buf: [i(1156)][j(36)][d] = 9248
constexpr int OFF_QS = 0;                        // 2 bufs
constexpr int OFF_RP = 2 * QSB;                  // 18688
constexpr int OFF_SC = OFF_RP + 2 * RPB;         // 37184 ; sc [64][260]
constexpr int SCS = 260;
constexpr int A_SMEM_FLOATS = OFF_SC + 64 * SCS; // 53824
constexpr int A_SMEM_BYTES  = A_SMEM_FLOATS * 4; // 215,296 B -> 1 CTA/SM

__global__ void __launch_bounds__(512, 1) attn_k(const float* __restrict__ rpe,
                                                 const int* __restrict__ snp)
{
    extern __shared__ float sm[];
    float* sc = sm + OFF_SC;
    const int tid = threadIdx.x;
    const int w = tid >> 5, lane = tid & 31;
    const int il = lane >> 3, h = lane & 7;
    const int b = blockIdx.y, i0 = blockIdx.x * 8;
    int sn = *snp; if (sn > 256) sn = 256; if (sn < 0) sn = 0;
    const int nt = (sn + JT - 1) / JT;            // <= 8
    const float scale = 0.17677669529663687f;     // 1/sqrt(32)

    // k rows for (il, h) and (il+4, h): 2 x 32 floats packed as f32x2
    ull kp0[16], kp1[16];
    {
        const float* kg0 = g_k + (size_t)(b * S_ + i0 + il) * DM_ + h * 32;
        const float* kg1 = kg0 + (size_t)4 * DM_;
        #pragma unroll
        for (int t = 0; t < 8; t++) {
            float4 a = *(const float4*)(kg0 + t * 4);
            kp0[2 * t] = pack2(a.x, a.y); kp0[2 * t + 1] = pack2(a.z, a.w);
            float4 c = *(const float4*)(kg1 + t * 4);
            kp1[2 * t] = pack2(c.x, c.y); kp1[2 * t + 1] = pack2(c.z, c.w);
        }
    }

    auto stage_qv = [&](const float* src_base, int t){    // 32 rows, head-padded
        int buf = t & 1, j0 = t * JT;
        #pragma unroll
        for (int r = 0; r < 4; r++) {
            int f = r * 512 + tid; int row = f >> 6, cq = f & 63;
            cpa16(sm + OFF_QS + buf * QSB + row * 292 + (cq >> 3) * 36 + (cq & 7) * 4,
                  src_base + (size_t)(b * S_ + j0 + row) * DM_ + cq * 4);
        }
    };
    auto stage_rpe = [&](int t){                          // 8 i x 32 j x 32 d
        int buf = t & 1, j0 = t * JT;
        #pragma unroll
        for (int r = 0; r < 4; r++) {
            int f = r * 512 + tid; int ii = f >> 8, j = (f >> 3) & 31, dq = f & 7;
            cpa16(sm + OFF_RP + buf * RPB + ii * 1156 + j * 36 + dq * 4,
                  rpe + ((size_t)(b * S_ + i0 + ii) * S_ + j0 + j) * D_ + dq * 4);
        }
    };

    if (nt > 0) { stage_qv(g_q, 0); stage_rpe(0); cpa_commit(); }
    if (nt > 1) { stage_qv(g_q, 1); stage_rpe(1); cpa_commit(); }

    // ---------------- score phase: warp covers j = {w, w+16} ----------------
    for (int t = 0; t < nt; t++) {
        if (t + 1 < nt) cpa_wait<1>(); else cpa_wait<0>();
        __syncthreads();
        const int buf = t & 1;
        #pragma unroll
        for (int jj = 0; jj < 2; jj++) {
            const int j = w + jj * 16, jg = t * JT + j;
            const float* qrow = sm + OFF_QS + buf * QSB + j * 292 + h * 36;
            const float* rp0  = sm + OFF_RP + buf * RPB + il * 1156 + j * 36;
            const float* rp1  = rp0 + 4 * 1156;
            ull a0 = 0ull, a1 = 0ull;
            #pragma unroll
            for (int d4 = 0; d4 < 8; d4++) {
                ulonglong2 q2 = *(const ulonglong2*)(qrow + d4 * 4);
                ulonglong2 r0 = *(const ulonglong2*)(rp0 + d4 * 4);
                a0 = fma2(mul2(q2.x, kp0[2 * d4]),     r0.x, a0);
                a0 = fma2(mul2(q2.y, kp0[2 * d4 + 1]), r0.y, a0);
                ulonglong2 r1 = *(const ulonglong2*)(rp1 + d4 * 4);
                a1 = fma2(mul2(q2.x, kp1[2 * d4]),     r1.x, a1);
                a1 = fma2(mul2(q2.y, kp1[2 * d4 + 1]), r1.y, a1);
            }
            if (jg < sn) {
                float2 t0 = unp2(a0), t1 = unp2(a1);
                sc[(il * 8 + h) * SCS + jg]       = (t0.x + t0.y) * scale;
                sc[((il + 4) * 8 + h) * SCS + jg] = (t1.x + t1.y) * scale;
            }
        }
        __syncthreads();
        if (t + 2 < nt) { stage_qv(g_q, t + 2); stage_rpe(t + 2); cpa_commit(); }
    }

    // prefetch v tiles 0,1 (overlaps diag + softmax)
    if (nt > 0) { stage_qv(g_v, 0); cpa_commit(); }
    if (nt > 1) { stage_qv(g_v, 1); cpa_commit(); }

    // diagonal column (needed when row i0+i >= sn); operands from gmem/L2
    if (tid < 64) {
        int di = tid >> 3, dh = tid & 7;
        int ig = i0 + di;
        if (ig >= sn) {
            const float* qg = g_q + (size_t)(b * S_ + ig) * DM_ + dh * 32;
            const float* kg = g_k + (size_t)(b * S_ + ig) * DM_ + dh * 32;
            const float* rg = rpe + ((size_t)(b * S_ + ig) * S_ + ig) * D_;
            ull acc = 0ull;
            #pragma unroll
            for (int t = 0; t < 8; t++) {
                float4 qf = *(const float4*)(qg + t * 4);
                float4 kf = *(const float4*)(kg + t * 4);
                float4 rf = *(const float4*)(rg + t * 4);
                acc = fma2(mul2(pack2(qf.x, qf.y), pack2(kf.x, kf.y)), pack2(rf.x, rf.y), acc);
                acc = fma2(mul2(pack2(qf.z, qf.w), pack2(kf.z, kf.w)), pack2(rf.z, rf.w), acc);
            }
            float2 tt = unp2(acc);
            sc[(di * 8 + dh) * SCS + 256] = (tt.x + tt.y) * scale;
        }
    }
    __syncthreads();

    // ---------------- softmax (16 warps x 4 rows = 64 rows) ----------------
    {
        const int jmax = nt * JT;
        for (int rr = 0; rr < 4; rr++) {
            int row = w * 4 + rr;
            bool hd = (i0 + (row >> 3)) >= sn;
            float* srow = &sc[row * SCS];
            float mx = -1e30f;
            for (int jj = lane; jj < sn; jj += 32) mx = fmaxf(mx, srow[jj]);
            if (hd && lane == 0) mx = fmaxf(mx, srow[256]);
            #pragma unroll
            for (int o = 16; o > 0; o >>= 1) mx = fmaxf(mx, __shfl_xor_sync(0xffffffffu, mx, o));
            float sum = 0.f;
            for (int jj = lane; jj < jmax; jj += 32) {
                float p = (jj < sn) ? __expf(srow[jj] - mx) : 0.f;
                srow[jj] = p; sum += p;
            }
            if (hd && lane == 0) { float p = __expf(srow[256] - mx); srow[256] = p; sum += p; }
            #pragma unroll
            for (int o = 16; o > 0; o >>= 1) sum += __shfl_xor_sync(0xffffffffu, sum, o);
            float rn = 1.f / sum;
            for (int jj = lane; jj < jmax; jj += 32) srow[jj] *= rn;
            if (hd && lane == 0) srow[256] *= rn;
        }
    }

    // ------- AV phase: thread owns (i = tid>>6, h = (tid>>3)&7, dc = tid&7) -
    const int ai = tid >> 6, ah = (tid >> 3) & 7, dc = tid & 7;
    ull a0 = 0ull, a1 = 0ull;
    for (int t = 0; t < nt; t++) {
        if (t + 1 < nt) cpa_wait<1>(); else cpa_wait<0>();
        __syncthreads();
        const float* vb = sm + OFF_QS + (t & 1) * QSB;
        #pragma unroll
        for (int g = 0; g < 8; g++) {
            float4 p4 = *(const float4*)&sc[(ai * 8 + ah) * SCS + t * JT + g * 4];
            const float pv[4] = {p4.x, p4.y, p4.z, p4.w};
            #pragma unroll
            for (int jj = 0; jj < 4; jj++) {
                ulonglong2 v2 = *(const ulonglong2*)(vb + (g * 4 + jj) * 292 + ah * 36 + dc * 4);
                ull pk = pack2(pv[jj], pv[jj]);
                a0 = fma2(pk, v2.x, a0);
                a1 = fma2(pk, v2.y, a1);
            }
        }
        __syncthreads();
        if (t + 2 < nt) { stage_qv(g_v, t + 2); cpa_commit(); }
    }
    // diagonal term + store
    {
        int ig = i0 + ai;
        if (ig >= sn) {
            float p = sc[(ai * 8 + ah) * SCS + 256];
            float4 vd = *(const float4*)(g_v + (size_t)(b * S_ + ig) * DM_ + ah * 32 + dc * 4);
            ull pk = pack2(p, p);
            a0 = fma2(pk, pack2(vd.x, vd.y), a0);
            a1 = fma2(pk, pack2(vd.z, vd.w), a1);
        }
        float2 lo = unp2(a0), hi = unp2(a1);
        float4 o; o.x = lo.x; o.y = lo.y; o.z = hi.x; o.w = hi.y;
        *(float4*)(g_ao + (size_t)(b * S_ + ig) * DM_ + ah * 32 + dc * 4) = o;
    }
}

// ---------------------------------------------------------------------------
// Kernel 3: epilogue GEMM + global barrier + layernorm (one kernel).
// GEMM: 32x32 tiles, 128 threads, grid (8 n, 32 m) = 256 blocks, depth-3.
// Then epoch flag-barrier (all 256 blocks resident: 128 thr, 27KB smem ->
// >=2 CTAs/SM so no deadlock), then each block layernorms 4 rows.
// ---------------------------------------------------------------------------
__global__ void __launch_bounds__(128) epi_k(const float* __restrict__ hs,
                                             const float* __restrict__ fw,
                                             const float* __restrict__ fb,
                                             const float* __restrict__ lw,
                                             const float* __restrict__ lb,
                                             float* __restrict__ out)
{
    __shared__ float es[6 * 1152];    // 3 A bufs + 3 B bufs, each 32x36
    const int tid = threadIdx.x, tx = tid & 7, ty = tid >> 3;
    const int n0 = blockIdx.x * 32, m0 = blockIdx.y * 32;

    auto stage = [&](int kt){
        int buf = kt % 3, k0 = kt * 32;
        float* As = es + buf * 1152;
        float* Bs = es + 3 * 1152 + buf * 1152;
        #pragma unroll
        for (int r = 0; r < 2; r++) {            // A: 32x32 = 256 chunks
            int f = r * 128 + tid; int row = f >> 3, kq = f & 7;
            cpa16(As + row * 36 + kq * 4, g_ao + (size_t)(m0 + row) * DM_ + k0 + kq * 4);
        }
        #pragma unroll
        for (int r = 0; r < 2; r++) {            // B: 32x32 = 256 chunks
            int f = r * 128 + tid; int kk = f >> 3, nq = f & 7;
            cpa16(Bs + kk * 36 + nq * 4, fw + (size_t)(k0 + kk) * DM_ + n0 + nq * 4);
        }
    };

    ull acc[2][2];
    acc[0][0] = acc[0][1] = acc[1][0] = acc[1][1] = 0ull;

    stage(0); cpa_commit();
    stage(1); cpa_commit();
    stage(2); cpa_commit();

    for (int kt = 0; kt < 8; kt++) {
        if (kt + 2 < 8) cpa_wait<2>(); else if (kt + 1 < 8) cpa_wait<1>(); else cpa_wait<0>();
        __syncthreads();
        const float* As = es + (kt % 3) * 1152;
        const float* Bs = es + 3 * 1152 + (kt % 3) * 1152;
        #pragma unroll
        for (int k4 = 0; k4 < 8; k4++) {
            ulonglong2 bR[4];
            #pragma unroll
            for (int kk = 0; kk < 4; kk++)
                bR[kk] = *(const ulonglong2*)(Bs + (k4 * 4 + kk) * 36 + tx * 4);
            #pragma unroll
            for (int r = 0; r < 2; r++) {
                float4 a4 = *(const float4*)(As + (ty * 2 + r) * 36 + k4 * 4);
                acc[r][0] = fma2(pack2(a4.x, a4.x), bR[0].x, acc[r][0]);
                acc[r][1] = fma2(pack2(a4.x, a4.x), bR[0].y, acc[r][1]);
                acc[r][0] = fma2(pack2(a4.y, a4.y), bR[1].x, acc[r][0]);
                acc[r][1] = fma2(pack2(a4.y, a4.y), bR[1].y, acc[r][1]);
                acc[r][0] = fma2(pack2(a4.z, a4.z), bR[2].x, acc[r][0]);
                acc[r][1] = fma2(pack2(a4.z, a4.z), bR[2].y, acc[r][1]);
                acc[r][0] = fma2(pack2(a4.w, a4.w), bR[3].x, acc[r][0]);
                acc[r][1] = fma2(pack2(a4.w, a4.w), bR[3].y, acc[r][1]);
            }
        }
        __syncthreads();
        if (kt + 3 < 8) { stage(kt + 3); cpa_commit(); }
    }

    // bias + residual -> g_cx
    float4 fb4 = *(const float4*)(fb + n0 + tx * 4);
    #pragma unroll
    for (int r = 0; r < 2; r++) {
        int row = m0 + ty * 2 + r;
        float4 h4 = *(const float4*)(hs + (size_t)row * DM_ + n0 + tx * 4);
        float2 lo = unp2(acc[r][0]), hi = unp2(acc[r][1]);
        float4 o;
        o.x = lo.x + fb4.x + h4.x; o.y = lo.y + fb4.y + h4.y;
        o.z = hi.x + fb4.z + h4.z; o.w = hi.y + fb4.w + h4.w;
        *(float4*)(g_cx + (size_t)row * DM_ + n0 + tx * 4) = o;
    }

    // ---- global flag barrier (epoch-based; monotonic, no reset needed) ----
    __threadfence();
    if (tid == 0) {
        unsigned old = atomicAdd(&g_bar, 1u);
        unsigned tgt = ((old >> 8) + 1u) << 8;           // (old/256+1)*256
        volatile unsigned* p = &g_bar;
        while (*p < tgt) { }
    }
    __syncthreads();
    __threadfence();

    // ---- layernorm: this block handles 4 rows (warp per row) ----
    {
        const int bid = blockIdx.y * 8 + blockIdx.x;     // 0..255
        const int w = tid >> 5, lane = tid & 31;
        const int row = bid * 4 + w;
        const float* xr = g_cx + (size_t)row * DM_ + lane * 8;
        float4 x0 = *(const float4*)xr;
        float4 x1 = *(const float4*)(xr + 4);
        float s = x0.x + x0.y + x0.z + x0.w + x1.x + x1.y + x1.z + x1.w;
        #pragma unroll
        for (int o = 16; o > 0; o >>= 1) s += __shfl_xor_sync(0xffffffffu, s, o);
        float mu = s * (1.f / 256.f);
        float xs[8] = {x0.x, x0.y, x0.z, x0.w, x1.x, x1.y, x1.z, x1.w};
        float v = 0.f;
        #pragma unroll
        for (int k = 0; k < 8; k++) { float d = xs[k] - mu; v += d * d; }
        #pragma unroll
        for (int o = 16; o > 0; o >>= 1) v += __shfl_xor_sync(0xffffffffu, v, o);
        float rs = rsqrtf(v * (1.f / 256.f) + 1e-6f);
        const int c = lane * 8;
        float4 lw0 = *(const float4*)(lw + c), lw1 = *(const float4*)(lw + c + 4);
        float4 lb0 = *(const float4*)(lb + c), lb1 = *(const float4*)(lb + c + 4);
        float4 y0, y1;
        y0.x = (xs[0]-mu)*rs*lw0.x + lb0.x; y0.y = (xs[1]-mu)*rs*lw0.y + lb0.y;
        y0.z = (xs[2]-mu)*rs*lw0.z + lb0.z; y0.w = (xs[3]-mu)*rs*lw0.w + lb0.w;
        y1.x = (xs[4]-mu)*rs*lw1.x + lb1.x; y1.y = (xs[5]-mu)*rs*lw1.y + lb1.y;
        y1.z = (xs[6]-mu)*rs*lw1.z + lb1.z; y1.w = (xs[7]-mu)*rs*lw1.w + lb1.w;
        size_t ro = (size_t)row * DM_ + c;
        *(float4*)(out + ro)     = y0;
        *(float4*)(out + ro + 4) = y1;
    }
}

// ---------------------------------------------------------------------------
extern "C" void kernel_launch(void* const* d_in, const int* in_sizes, int n_in,
                              void* d_out, int out_size)
{
    const float* hs  = (const float*)d_in[0];
    const float* rpe = (const float*)d_in[1];
    const float* wq  = (const float*)d_in[2];
    const float* wk  = (const float*)d_in[3];
    const float* wv  = (const float*)d_in[4];
    const float* fw  = (const float*)d_in[5];
    const float* fb  = (const float*)d_in[6];
    const float* lw  = (const float*)d_in[7];
    const float* lb  = (const float*)d_in[8];
    const int*   sn  = (const int*)  d_in[9];
    float* out = (float*)d_out;

    cudaFuncSetAttribute(attn_k, cudaFuncAttributeMaxDynamicSharedMemorySize, A_SMEM_BYTES);

    qkv_k<<<dim3(4, 32, 3), 128>>>(hs, wq, wk, wv);
    attn_k<<<dim3(64, 2), 512, A_SMEM_BYTES>>>(rpe, sn);
    epi_k<<<dim3(8, 32), 128>>>(hs, fw, fb, lw, lb, out);
}